// round 4
// baseline (speedup 1.0000x reference)
#include <cuda_runtime.h>
#include <cstdint>
#include <cstddef>

// ---------------- problem constants ----------------
#define NN   100000            // nodes
#define NE   1600000           // original edges
#define NE2  1700000           // edges + self loops

// ---------------- device scratch (no allocations allowed) ----------------
__device__ __align__(16) float    g_ea_mean[NN * 16];
__device__            float       g_deg[NN];
__device__ __align__(16) float    g_xl[NN * 64];
__device__ __align__(16) float    g_xr[NN * 64];
__device__ __align__(16) float    g_h[NN * 64];      // conv1 numerator accum, then h
__device__            float       g_score[(size_t)NE2 * 8];
__device__            unsigned    g_mkey[NN * 8];    // order-preserving float max keys
__device__            float       g_s[NN * 8];       // softmax denominators

// ---------------- helpers ----------------
__device__ __forceinline__ unsigned fkey(float f) {
    unsigned u = __float_as_uint(f);
    return (u & 0x80000000u) ? ~u : (u | 0x80000000u);   // monotone float->uint
}
__device__ __forceinline__ float funkey(unsigned k) {
    return (k & 0x80000000u) ? __uint_as_float(k & 0x7fffffffu)
                             : __uint_as_float(~k);
}

// ---------------- init ----------------
__global__ void k_init1() {
    int i = blockIdx.x * blockDim.x + threadIdx.x;
    if (i < NN) g_deg[i] = 0.f;
    if (i < NN * 8)  { g_mkey[i] = 0u; g_s[i] = 0.f; }
    if (i < NN * 16) g_ea_mean[i] = 0.f;
    if (i < NN * 64) g_h[i] = 0.f;
}

__global__ void k_init2(float* __restrict__ out) {
    int i = blockIdx.x * blockDim.x + threadIdx.x;
    if (i >= NN * 64) return;
    out[i] = 0.f;
    if (i < NN) { g_mkey[i] = 0u; g_s[i] = 0.f; }
}

// ---------------- self-loop edge_attr mean ----------------
__global__ void k_deg_ea(const int* __restrict__ ei,
                         const float* __restrict__ ea) {
    int e = blockIdx.x * blockDim.x + threadIdx.x;
    if (e >= NE) return;
    int dst = ei[NE + e];
    atomicAdd(&g_deg[dst], 1.0f);
    const float4* v4 = (const float4*)(ea + (size_t)e * 16);
    float* o = g_ea_mean + (size_t)dst * 16;
#pragma unroll
    for (int i = 0; i < 4; i++) {
        float4 v = v4[i];
        atomicAdd(o + 4 * i + 0, v.x);
        atomicAdd(o + 4 * i + 1, v.y);
        atomicAdd(o + 4 * i + 2, v.z);
        atomicAdd(o + 4 * i + 3, v.w);
    }
}

__global__ void k_ea_norm() {
    int i = blockIdx.x * blockDim.x + threadIdx.x;
    if (i >= NN * 16) return;
    float d = g_deg[i >> 4];
    g_ea_mean[i] /= fmaxf(d, 1.0f);
}

// ---------------- GEMM: C[n,64] = A[n,K] @ W[K,64] + bias ----------------
// ASEL: 0 -> external A (x), 1 -> g_h.   CSEL: 0 -> g_xl, 1 -> g_xr.
template <int K, int ASEL, int CSEL>
__global__ void k_gemm64(const float* __restrict__ Aext,
                         const float* __restrict__ W,
                         const float* __restrict__ bias, int nrows) {
    const float* A = (ASEL == 0) ? Aext : (const float*)g_h;
    float*       C = (CSEL == 0) ? g_xl : g_xr;
    __shared__ float As[64 * 33];
    __shared__ float Ws[32 * 64];
    __shared__ float bs[64];
    int tid  = threadIdx.x;
    int row0 = blockIdx.x * 64;
    if (tid < 64) bs[tid] = bias[tid];
    int tc = tid & 31;       // col (and col+32)
    int tr = tid >> 5;       // row group 0..7 (8 rows each)
    float acc[8][2];
#pragma unroll
    for (int r = 0; r < 8; r++) { acc[r][0] = 0.f; acc[r][1] = 0.f; }

    for (int k0 = 0; k0 < K; k0 += 32) {
        __syncthreads();
#pragma unroll
        for (int i = 0; i < 8; i++) {
            int lin = tid + i * 256;
            int r = lin >> 5, kk = lin & 31;
            int gr = row0 + r;
            As[r * 33 + kk] = (gr < nrows) ? A[(size_t)gr * K + k0 + kk] : 0.f;
        }
#pragma unroll
        for (int i = 0; i < 8; i++) {
            int lin = tid + i * 256;
            int kk = lin >> 6, j = lin & 63;
            Ws[kk * 64 + j] = W[(size_t)(k0 + kk) * 64 + j];
        }
        __syncthreads();
#pragma unroll
        for (int kk = 0; kk < 32; kk++) {
            float w0 = Ws[kk * 64 + tc];
            float w1 = Ws[kk * 64 + tc + 32];
#pragma unroll
            for (int r = 0; r < 8; r++) {
                float xv = As[(tr * 8 + r) * 33 + kk];
                acc[r][0] = fmaf(xv, w0, acc[r][0]);
                acc[r][1] = fmaf(xv, w1, acc[r][1]);
            }
        }
    }
#pragma unroll
    for (int r = 0; r < 8; r++) {
        int gr = row0 + tr * 8 + r;
        if (gr < nrows) {
            C[(size_t)gr * 64 + tc]      = acc[r][0] + bs[tc];
            C[(size_t)gr * 64 + tc + 32] = acc[r][1] + bs[tc + 32];
        }
    }
}

// ---------------- conv1 pass 1: scores + segment max (warp/edge) ----------------
__global__ void k_c1_score(const int* __restrict__ ei,
                           const float* __restrict__ ea,
                           const float* __restrict__ We,
                           const float* __restrict__ att) {
    __shared__ float Ws[16 * 64];
    __shared__ float atts[64];
    int tid = threadIdx.x;
    for (int i = tid; i < 16 * 64; i += 256) Ws[i] = We[i];
    if (tid < 64) atts[tid] = att[tid];
    __syncthreads();

    int gw = (blockIdx.x * 256 + tid) >> 5;
    if (gw >= NE2) return;
    int lane = tid & 31;

    int src, dst; const float* ear;
    if (gw < NE) {
        src = ei[gw];
        dst = ei[NE + gw];
        ear = ea + (size_t)gw * 16;
    } else {
        src = dst = gw - NE;
        ear = g_ea_mean + (size_t)src * 16;
    }

    float eav = (lane < 16) ? ear[lane] : 0.f;
    float ee0 = 0.f, ee1 = 0.f;
#pragma unroll
    for (int k = 0; k < 16; k++) {
        float a  = __shfl_sync(0xffffffffu, eav, k);
        float2 w = *(const float2*)&Ws[k * 64 + 2 * lane];
        ee0 = fmaf(a, w.x, ee0);
        ee1 = fmaf(a, w.y, ee1);
    }
    float2 xlv = *(const float2*)(g_xl + (size_t)src * 64 + 2 * lane);
    float2 xrv = *(const float2*)(g_xr + (size_t)dst * 64 + 2 * lane);
    float z0 = xlv.x + xrv.x + ee0; z0 = z0 > 0.f ? z0 : 0.2f * z0;
    float z1 = xlv.y + xrv.y + ee1; z1 = z1 > 0.f ? z1 : 0.2f * z1;
    float2 a2 = *(const float2*)&atts[2 * lane];
    float p = fmaf(z0, a2.x, z1 * a2.y);
    p += __shfl_xor_sync(0xffffffffu, p, 1);
    p += __shfl_xor_sync(0xffffffffu, p, 2);      // head reduction (8 ch = 4 lanes)
    if ((lane & 3) == 0) {
        int h = lane >> 2;
        g_score[(size_t)gw * 8 + h] = p;
        atomicMax(&g_mkey[dst * 8 + h], fkey(p));
    }
}

// ---------------- conv1 pass 2: exp + denominator + numerator ----------------
__global__ void k_c1_aggr(const int* __restrict__ ei) {
    int tid = threadIdx.x;
    int gw  = (blockIdx.x * 256 + tid) >> 5;
    if (gw >= NE2) return;
    int lane = tid & 31;

    int src, dst;
    if (gw < NE) { src = ei[gw]; dst = ei[NE + gw]; }
    else         { src = dst = gw - NE; }

    int h    = lane >> 2;
    float sc = g_score[(size_t)gw * 8 + h];
    float m  = funkey(g_mkey[dst * 8 + h]);
    float eh = __expf(sc - m);
    if ((lane & 3) == 0) atomicAdd(&g_s[dst * 8 + h], eh);
    float2 xlv = *(const float2*)(g_xl + (size_t)src * 64 + 2 * lane);
    float* o = g_h + (size_t)dst * 64 + 2 * lane;
    atomicAdd(o + 0, eh * xlv.x);
    atomicAdd(o + 1, eh * xlv.y);
}

// ---------------- conv1 finalize: divide + bias + ELU ----------------
__global__ void k_c1_fin(const float* __restrict__ b1) {
    int i = blockIdx.x * blockDim.x + threadIdx.x;
    if (i >= NN * 64) return;
    int n = i >> 6, j = i & 63;
    float s = g_s[n * 8 + (j >> 3)];
    float v = g_h[i] / (s + 1e-16f) + b1[j];
    g_h[i] = v > 0.f ? v : expm1f(v);
}

// ---------------- conv2 pass 1: single-head score + max ----------------
__global__ void k_c2_score(const int* __restrict__ ei,
                           const float* __restrict__ ea,
                           const float* __restrict__ We,
                           const float* __restrict__ att) {
    __shared__ float Ws[16 * 64];
    __shared__ float atts[64];
    int tid = threadIdx.x;
    for (int i = tid; i < 16 * 64; i += 256) Ws[i] = We[i];
    if (tid < 64) atts[tid] = att[tid];
    __syncthreads();

    int gw = (blockIdx.x * 256 + tid) >> 5;
    if (gw >= NE2) return;
    int lane = tid & 31;

    int src, dst; const float* ear;
    if (gw < NE) {
        src = ei[gw];
        dst = ei[NE + gw];
        ear = ea + (size_t)gw * 16;
    } else {
        src = dst = gw - NE;
        ear = g_ea_mean + (size_t)src * 16;
    }

    float eav = (lane < 16) ? ear[lane] : 0.f;
    float ee0 = 0.f, ee1 = 0.f;
#pragma unroll
    for (int k = 0; k < 16; k++) {
        float a  = __shfl_sync(0xffffffffu, eav, k);
        float2 w = *(const float2*)&Ws[k * 64 + 2 * lane];
        ee0 = fmaf(a, w.x, ee0);
        ee1 = fmaf(a, w.y, ee1);
    }
    float2 xlv = *(const float2*)(g_xl + (size_t)src * 64 + 2 * lane);
    float2 xrv = *(const float2*)(g_xr + (size_t)dst * 64 + 2 * lane);
    float z0 = xlv.x + xrv.x + ee0; z0 = z0 > 0.f ? z0 : 0.2f * z0;
    float z1 = xlv.y + xrv.y + ee1; z1 = z1 > 0.f ? z1 : 0.2f * z1;
    float2 a2 = *(const float2*)&atts[2 * lane];
    float p = fmaf(z0, a2.x, z1 * a2.y);
#pragma unroll
    for (int o = 1; o < 32; o <<= 1) p += __shfl_xor_sync(0xffffffffu, p, o);
    if (lane == 0) {
        g_score[gw] = p;
        atomicMax(&g_mkey[dst], fkey(p));
    }
}

// ---------------- conv2 pass 2: exp + denom + numerator into d_out ----------------
__global__ void k_c2_aggr(const int* __restrict__ ei, float* __restrict__ out) {
    int tid = threadIdx.x;
    int gw  = (blockIdx.x * 256 + tid) >> 5;
    if (gw >= NE2) return;
    int lane = tid & 31;

    int src, dst;
    if (gw < NE) { src = ei[gw]; dst = ei[NE + gw]; }
    else         { src = dst = gw - NE; }

    float sc = g_score[gw];
    float m  = funkey(g_mkey[dst]);
    float eh = __expf(sc - m);
    if (lane == 0) atomicAdd(&g_s[dst], eh);
    float2 xlv = *(const float2*)(g_xl + (size_t)src * 64 + 2 * lane);
    float* o = out + (size_t)dst * 64 + 2 * lane;
    atomicAdd(o + 0, eh * xlv.x);
    atomicAdd(o + 1, eh * xlv.y);
}

// ---------------- conv2 finalize ----------------
__global__ void k_c2_fin(float* __restrict__ out, const float* __restrict__ b2) {
    int i = blockIdx.x * blockDim.x + threadIdx.x;
    if (i >= NN * 64) return;
    int n = i >> 6, j = i & 63;
    out[i] = out[i] / (g_s[n] + 1e-16f) + b2[j];
}

// ---------------- launch (kernel launches ONLY — no runtime API calls) --------
extern "C" void kernel_launch(void* const* d_in, const int* in_sizes, int n_in,
                              void* d_out, int out_size) {
    (void)in_sizes; (void)n_in; (void)out_size;
    const float* x    = (const float*)d_in[0];
    const int*   ei   = (const int*)d_in[1];     // int32: JAX x64 disabled downcasts int64
    const float* ea   = (const float*)d_in[2];
    const float* Wl1  = (const float*)d_in[3];
    const float* bl1  = (const float*)d_in[4];
    const float* Wr1  = (const float*)d_in[5];
    const float* br1  = (const float*)d_in[6];
    const float* We1  = (const float*)d_in[7];
    const float* att1 = (const float*)d_in[8];
    const float* b1   = (const float*)d_in[9];
    const float* Wl2  = (const float*)d_in[10];
    const float* bl2  = (const float*)d_in[11];
    const float* Wr2  = (const float*)d_in[12];
    const float* br2  = (const float*)d_in[13];
    const float* We2  = (const float*)d_in[14];
    const float* att2 = (const float*)d_in[15];
    const float* b2   = (const float*)d_in[16];
    float* out = (float*)d_out;

    const int TB = 256;
    const int edge_blocks = (NE2 + 7) / 8;   // warp per edge, 8 warps/block

    k_init1<<<(NN * 64 + TB - 1) / TB, TB>>>();
    k_deg_ea<<<(NE + TB - 1) / TB, TB>>>(ei, ea);
    k_ea_norm<<<(NN * 16 + TB - 1) / TB, TB>>>();

    // conv1 linear projections: xl = x@Wl1+bl1, xr = x@Wr1+br1
    k_gemm64<128, 0, 0><<<(NN + 63) / 64, 256>>>(x, Wl1, bl1, NN);
    k_gemm64<128, 0, 1><<<(NN + 63) / 64, 256>>>(x, Wr1, br1, NN);

    k_c1_score<<<edge_blocks, 256>>>(ei, ea, We1, att1);
    k_c1_aggr<<<edge_blocks, 256>>>(ei);
    k_c1_fin<<<(NN * 64 + TB - 1) / TB, TB>>>(b1);

    k_init2<<<(NN * 64 + TB - 1) / TB, TB>>>(out);

    // conv2 linear projections from g_h (ASEL=1)
    k_gemm64<64, 1, 0><<<(NN + 63) / 64, 256>>>(nullptr, Wl2, bl2, NN);
    k_gemm64<64, 1, 1><<<(NN + 63) / 64, 256>>>(nullptr, Wr2, br2, NN);

    k_c2_score<<<edge_blocks, 256>>>(ei, ea, We2, att2);
    k_c2_aggr<<<edge_blocks, 256>>>(ei, out);
    k_c2_fin<<<(NN * 64 + TB - 1) / TB, TB>>>(out, b2);
}

// round 5
// speedup vs baseline: 1.5516x; 1.5516x over previous
#include <cuda_runtime.h>
#include <cstdint>
#include <cstddef>

// ---------------- problem constants ----------------
#define NN   100000            // nodes
#define NE   1600000           // original edges (self-loops handled explicitly)

// ---------------- device scratch (no allocations allowed) ----------------
__device__            int      g_cnt[NN];        // in-degree (histogram)
__device__            int      g_rowptr[NN];     // CSR row starts
__device__            int      g_pos[NN];        // scatter cursors
__device__            int      g_eid[NE];        // edge ids grouped by dst
__device__            int      g_esrc[NE];       // src ids grouped by dst
__device__ __align__(16) float g_ea_mean[NN * 16];
__device__ __align__(16) float g_xl[NN * 64];
__device__ __align__(16) float g_xr[NN * 64];
__device__ __align__(16) float g_h[NN * 64];

// ---------------- CSR build ----------------
__global__ void k_zero_cnt() {
    int i = blockIdx.x * blockDim.x + threadIdx.x;
    if (i < NN) g_cnt[i] = 0;
}

__global__ void k_hist(const int* __restrict__ ei) {
    int e = blockIdx.x * blockDim.x + threadIdx.x;
    if (e >= NE) return;
    atomicAdd(&g_cnt[ei[NE + e]], 1);
}

// single-block exclusive scan over g_cnt -> g_rowptr, g_pos
__global__ void k_scan() {
    __shared__ int ps[1024];
    const int CH = (NN + 1023) / 1024;           // 98
    int t   = threadIdx.x;
    int beg = t * CH;
    int end = beg + CH < NN ? beg + CH : NN;
    int s = 0;
    for (int i = beg; i < end; i++) s += g_cnt[i];
    ps[t] = s;
    __syncthreads();
    for (int off = 1; off < 1024; off <<= 1) {
        int v = (t >= off) ? ps[t - off] : 0;
        __syncthreads();
        ps[t] += v;
        __syncthreads();
    }
    int base = ps[t] - s;                        // exclusive
    for (int i = beg; i < end; i++) {
        g_rowptr[i] = base;
        g_pos[i]    = base;
        base += g_cnt[i];
    }
}

__global__ void k_scatter(const int* __restrict__ ei) {
    int e = blockIdx.x * blockDim.x + threadIdx.x;
    if (e >= NE) return;
    int src = ei[e];
    int dst = ei[NE + e];
    int idx = atomicAdd(&g_pos[dst], 1);
    g_eid[idx]  = e;
    g_esrc[idx] = src;
}

// ---------------- per-node mean of incoming edge_attr (no atomics) ----------
__global__ void k_eamean(const float* __restrict__ ea) {
    int w = (blockIdx.x * blockDim.x + threadIdx.x) >> 5;
    if (w >= NN) return;
    int lane = threadIdx.x & 31;
    int beg = g_rowptr[w], cnt = g_cnt[w];
    float s = 0.f;
    if (lane < 16) {
        for (int i = beg; i < beg + cnt; i++) {
            int eid = g_eid[i];
            s += ea[(size_t)eid * 16 + lane];
        }
        g_ea_mean[w * 16 + lane] = s / (float)(cnt > 0 ? cnt : 1);
    }
}

// ---------------- GEMM: C[n,64] = A[n,K] @ W[K,64] + bias ----------------
// ASEL: 0 -> external A (x), 1 -> g_h.   CSEL: 0 -> g_xl, 1 -> g_xr.
template <int K, int ASEL, int CSEL>
__global__ void k_gemm64(const float* __restrict__ Aext,
                         const float* __restrict__ W,
                         const float* __restrict__ bias, int nrows) {
    const float* A = (ASEL == 0) ? Aext : (const float*)g_h;
    float*       C = (CSEL == 0) ? g_xl : g_xr;
    __shared__ float As[64 * 33];
    __shared__ float Ws[32 * 64];
    __shared__ float bs[64];
    int tid  = threadIdx.x;
    int row0 = blockIdx.x * 64;
    if (tid < 64) bs[tid] = bias[tid];
    int tc = tid & 31;
    int tr = tid >> 5;
    float acc[8][2];
#pragma unroll
    for (int r = 0; r < 8; r++) { acc[r][0] = 0.f; acc[r][1] = 0.f; }

    for (int k0 = 0; k0 < K; k0 += 32) {
        __syncthreads();
#pragma unroll
        for (int i = 0; i < 8; i++) {
            int lin = tid + i * 256;
            int r = lin >> 5, kk = lin & 31;
            int gr = row0 + r;
            As[r * 33 + kk] = (gr < nrows) ? A[(size_t)gr * K + k0 + kk] : 0.f;
        }
#pragma unroll
        for (int i = 0; i < 8; i++) {
            int lin = tid + i * 256;
            int kk = lin >> 6, j = lin & 63;
            Ws[kk * 64 + j] = W[(size_t)(k0 + kk) * 64 + j];
        }
        __syncthreads();
#pragma unroll
        for (int kk = 0; kk < 32; kk++) {
            float w0 = Ws[kk * 64 + tc];
            float w1 = Ws[kk * 64 + tc + 32];
#pragma unroll
            for (int r = 0; r < 8; r++) {
                float xv = As[(tr * 8 + r) * 33 + kk];
                acc[r][0] = fmaf(xv, w0, acc[r][0]);
                acc[r][1] = fmaf(xv, w1, acc[r][1]);
            }
        }
    }
#pragma unroll
    for (int r = 0; r < 8; r++) {
        int gr = row0 + tr * 8 + r;
        if (gr < nrows) {
            C[(size_t)gr * 64 + tc]      = acc[r][0] + bs[tc];
            C[(size_t)gr * 64 + tc + 32] = acc[r][1] + bs[tc + 32];
        }
    }
}

// ---------------- fused GATv2 layer, warp per destination node -------------
// HEADS8: 1 -> 8 heads of 8ch (reduce over 4-lane groups), 0 -> 1 head of 64.
// OUTMODE: 0 -> write g_h with bias+ELU (layer1), 1 -> write out with bias.
template <int HEADS8, int OUTMODE>
__global__ void k_node(const float* __restrict__ ea,
                       const float* __restrict__ We,
                       const float* __restrict__ att,
                       const float* __restrict__ bias,
                       float* __restrict__ out) {
    __shared__ float Ws[16 * 64];
    __shared__ float atts[64];
    __shared__ float bs[64];
    int tid = threadIdx.x;
    for (int i = tid; i < 16 * 64; i += 256) Ws[i] = We[i];
    if (tid < 64) { atts[tid] = att[tid]; bs[tid] = bias[tid]; }
    __syncthreads();

    int n = (blockIdx.x * 256 + tid) >> 5;
    if (n >= NN) return;
    int lane = tid & 31;
    int c0 = 2 * lane;

    float2 xr = *(const float2*)(g_xr + (size_t)n * 64 + c0);
    float2 a2 = *(const float2*)&atts[c0];

    float den = 0.f, acc0 = 0.f, acc1 = 0.f;

    int beg = g_rowptr[n];
    int cnt = g_cnt[n];

    // iterate self-loop (i == beg+cnt) plus real edges
    for (int i = beg; i <= beg + cnt; i++) {
        int src;
        const float* ear;
        if (i < beg + cnt) {
            src = g_esrc[i];
            ear = ea + (size_t)g_eid[i] * 16;
        } else {
            src = n;
            ear = g_ea_mean + (size_t)n * 16;
        }
        float eav = (lane < 16) ? ear[lane] : 0.f;
        float ee0 = 0.f, ee1 = 0.f;
#pragma unroll
        for (int k = 0; k < 16; k++) {
            float a  = __shfl_sync(0xffffffffu, eav, k);
            float2 w = *(const float2*)&Ws[k * 64 + c0];
            ee0 = fmaf(a, w.x, ee0);
            ee1 = fmaf(a, w.y, ee1);
        }
        float2 xl = *(const float2*)(g_xl + (size_t)src * 64 + c0);
        float z0 = xl.x + xr.x + ee0; z0 = z0 > 0.f ? z0 : 0.2f * z0;
        float z1 = xl.y + xr.y + ee1; z1 = z1 > 0.f ? z1 : 0.2f * z1;
        float p = fmaf(z0, a2.x, z1 * a2.y);
        if (HEADS8) {
            p += __shfl_xor_sync(0xffffffffu, p, 1);
            p += __shfl_xor_sync(0xffffffffu, p, 2);
        } else {
#pragma unroll
            for (int o = 1; o < 32; o <<= 1) p += __shfl_xor_sync(0xffffffffu, p, o);
        }
        float eh = __expf(p);          // no max-shift: ratio is shift-invariant
        den  += eh;
        acc0 = fmaf(eh, xl.x, acc0);
        acc1 = fmaf(eh, xl.y, acc1);
    }

    float inv = 1.0f / (den + 1e-16f);
    float v0 = acc0 * inv + bs[c0];
    float v1 = acc1 * inv + bs[c0 + 1];
    if (OUTMODE == 0) {                // ELU for layer 1
        v0 = v0 > 0.f ? v0 : expm1f(v0);
        v1 = v1 > 0.f ? v1 : expm1f(v1);
        g_h[(size_t)n * 64 + c0]     = v0;
        g_h[(size_t)n * 64 + c0 + 1] = v1;
    } else {
        out[(size_t)n * 64 + c0]     = v0;
        out[(size_t)n * 64 + c0 + 1] = v1;
    }
}

// ---------------- launch (kernel launches ONLY) ----------------------------
extern "C" void kernel_launch(void* const* d_in, const int* in_sizes, int n_in,
                              void* d_out, int out_size) {
    (void)in_sizes; (void)n_in; (void)out_size;
    const float* x    = (const float*)d_in[0];
    const int*   ei   = (const int*)d_in[1];     // int32 (JAX x64 disabled)
    const float* ea   = (const float*)d_in[2];
    const float* Wl1  = (const float*)d_in[3];
    const float* bl1  = (const float*)d_in[4];
    const float* Wr1  = (const float*)d_in[5];
    const float* br1  = (const float*)d_in[6];
    const float* We1  = (const float*)d_in[7];
    const float* att1 = (const float*)d_in[8];
    const float* b1   = (const float*)d_in[9];
    const float* Wl2  = (const float*)d_in[10];
    const float* bl2  = (const float*)d_in[11];
    const float* Wr2  = (const float*)d_in[12];
    const float* br2  = (const float*)d_in[13];
    const float* We2  = (const float*)d_in[14];
    const float* att2 = (const float*)d_in[15];
    const float* b2   = (const float*)d_in[16];
    float* out = (float*)d_out;

    const int TB = 256;
    const int node_blocks = (NN * 32 + TB - 1) / TB;   // warp per node

    // CSR build
    k_zero_cnt<<<(NN + TB - 1) / TB, TB>>>();
    k_hist<<<(NE + TB - 1) / TB, TB>>>(ei);
    k_scan<<<1, 1024>>>();
    k_scatter<<<(NE + TB - 1) / TB, TB>>>(ei);
    k_eamean<<<node_blocks, TB>>>(ea);

    // layer 1
    k_gemm64<128, 0, 0><<<(NN + 63) / 64, 256>>>(x, Wl1, bl1, NN);
    k_gemm64<128, 0, 1><<<(NN + 63) / 64, 256>>>(x, Wr1, br1, NN);
    k_node<1, 0><<<node_blocks, TB>>>(ea, We1, att1, b1, out);

    // layer 2
    k_gemm64<64, 1, 0><<<(NN + 63) / 64, 256>>>(nullptr, Wl2, bl2, NN);
    k_gemm64<64, 1, 1><<<(NN + 63) / 64, 256>>>(nullptr, Wr2, br2, NN);
    k_node<0, 1><<<node_blocks, TB>>>(ea, We2, att2, b2, out);
}

// round 6
// speedup vs baseline: 1.8496x; 1.1921x over previous
#include <cuda_runtime.h>
#include <cstdint>
#include <cstddef>

// ---------------- problem constants ----------------
#define NN   100000            // nodes
#define NE   1600000           // original edges (self-loops handled explicitly)

// ---------------- device scratch (no allocations allowed) ----------------
__device__            int      g_cnt[NN];        // in-degree
__device__            int      g_rowptr[NN];     // CSR row starts
__device__            int      g_pos[NN];        // scatter cursors
__device__            int      g_esrc[NE];       // src ids grouped by dst
__device__ __align__(16) float g_eas[(size_t)NE * 16];  // edge attrs, CSR order
__device__ __align__(16) float g_ea_mean[NN * 16];
__device__ __align__(16) float g_xl[NN * 64];
__device__ __align__(16) float g_xr[NN * 64];
__device__ __align__(16) float g_h[NN * 64];

// ---------------- CSR build ----------------
__global__ void k_zero_cnt() {
    int i = blockIdx.x * blockDim.x + threadIdx.x;
    if (i < NN) g_cnt[i] = 0;
}

__global__ void k_hist(const int* __restrict__ ei) {
    int e = blockIdx.x * blockDim.x + threadIdx.x;
    if (e >= NE) return;
    atomicAdd(&g_cnt[ei[NE + e]], 1);
}

// single-block exclusive scan over g_cnt -> g_rowptr, g_pos
__global__ void k_scan() {
    __shared__ int ps[1024];
    const int CH = (NN + 1023) / 1024;           // 98
    int t   = threadIdx.x;
    int beg = t * CH;
    int end = beg + CH < NN ? beg + CH : NN;
    int s = 0;
    for (int i = beg; i < end; i++) s += g_cnt[i];
    ps[t] = s;
    __syncthreads();
    for (int off = 1; off < 1024; off <<= 1) {
        int v = (t >= off) ? ps[t - off] : 0;
        __syncthreads();
        ps[t] += v;
        __syncthreads();
    }
    int base = ps[t] - s;                        // exclusive
    for (int i = beg; i < end; i++) {
        g_rowptr[i] = base;
        g_pos[i]    = base;
        base += g_cnt[i];
    }
}

// scatter src ids AND edge attrs into CSR (dst-grouped) order
__global__ void k_scatter(const int* __restrict__ ei, const float* __restrict__ ea) {
    int e = blockIdx.x * blockDim.x + threadIdx.x;
    if (e >= NE) return;
    int src = ei[e];
    int dst = ei[NE + e];
    int idx = atomicAdd(&g_pos[dst], 1);
    g_esrc[idx] = src;
    const float4* v4 = (const float4*)(ea + (size_t)e * 16);
    float4* o4 = (float4*)(g_eas + (size_t)idx * 16);
    o4[0] = v4[0]; o4[1] = v4[1]; o4[2] = v4[2]; o4[3] = v4[3];
}

// ---------------- per-node mean of incoming edge_attr (contiguous) ----------
__global__ void k_eamean() {
    int w = (blockIdx.x * blockDim.x + threadIdx.x) >> 5;
    if (w >= NN) return;
    int lane = threadIdx.x & 31;
    int l    = lane & 15;
    int half = lane >> 4;
    int beg = g_rowptr[w], cnt = g_cnt[w];
    float s = 0.f;
    for (int i = beg + half; i < beg + cnt; i += 2)
        s += g_eas[(size_t)i * 16 + l];
    s += __shfl_xor_sync(0xffffffffu, s, 16);
    if (lane < 16)
        g_ea_mean[w * 16 + lane] = s / (float)(cnt > 0 ? cnt : 1);
}

// ---------------- GEMM: C[n,64] = A[n,K] @ W[K,64] + bias ----------------
template <int K, int ASEL, int CSEL>
__global__ void k_gemm64(const float* __restrict__ Aext,
                         const float* __restrict__ W,
                         const float* __restrict__ bias, int nrows) {
    const float* A = (ASEL == 0) ? Aext : (const float*)g_h;
    float*       C = (CSEL == 0) ? g_xl : g_xr;
    __shared__ float As[64 * 33];
    __shared__ float Ws[32 * 64];
    __shared__ float bs[64];
    int tid  = threadIdx.x;
    int row0 = blockIdx.x * 64;
    if (tid < 64) bs[tid] = bias[tid];
    int tc = tid & 31;
    int tr = tid >> 5;
    float acc[8][2];
#pragma unroll
    for (int r = 0; r < 8; r++) { acc[r][0] = 0.f; acc[r][1] = 0.f; }

    for (int k0 = 0; k0 < K; k0 += 32) {
        __syncthreads();
#pragma unroll
        for (int i = 0; i < 8; i++) {
            int lin = tid + i * 256;
            int r = lin >> 5, kk = lin & 31;
            int gr = row0 + r;
            As[r * 33 + kk] = (gr < nrows) ? A[(size_t)gr * K + k0 + kk] : 0.f;
        }
#pragma unroll
        for (int i = 0; i < 8; i++) {
            int lin = tid + i * 256;
            int kk = lin >> 6, j = lin & 63;
            Ws[kk * 64 + j] = W[(size_t)(k0 + kk) * 64 + j];
        }
        __syncthreads();
#pragma unroll
        for (int kk = 0; kk < 32; kk++) {
            float w0 = Ws[kk * 64 + tc];
            float w1 = Ws[kk * 64 + tc + 32];
#pragma unroll
            for (int r = 0; r < 8; r++) {
                float xv = As[(tr * 8 + r) * 33 + kk];
                acc[r][0] = fmaf(xv, w0, acc[r][0]);
                acc[r][1] = fmaf(xv, w1, acc[r][1]);
            }
        }
    }
#pragma unroll
    for (int r = 0; r < 8; r++) {
        int gr = row0 + tr * 8 + r;
        if (gr < nrows) {
            C[(size_t)gr * 64 + tc]      = acc[r][0] + bs[tc];
            C[(size_t)gr * 64 + tc + 32] = acc[r][1] + bs[tc + 32];
        }
    }
}

// ---------------- fused GATv2 layer, warp per destination node -------------
// HEADS8: 1 -> 8 heads of 8ch, 0 -> 1 head of 64ch.
// OUTMODE: 0 -> g_h with bias+ELU (layer1), 1 -> out with bias (layer2).
template <int HEADS8, int OUTMODE>
__global__ void k_node(const float* __restrict__ We,
                       const float* __restrict__ att,
                       const float* __restrict__ bias,
                       float* __restrict__ out) {
    __shared__ float Ws[16 * 64];
    __shared__ float atts[64];
    __shared__ float bs[64];
    int tid = threadIdx.x;
    for (int i = tid; i < 16 * 64; i += 256) Ws[i] = We[i];
    if (tid < 64) { atts[tid] = att[tid]; bs[tid] = bias[tid]; }
    __syncthreads();

    int n = (blockIdx.x * 256 + tid) >> 5;
    if (n >= NN) return;
    int lane = tid & 31;
    int c0 = 2 * lane;

    float2 xr = *(const float2*)(g_xr + (size_t)n * 64 + c0);
    float2 a2 = *(const float2*)&atts[c0];

    float den = 0.f, acc0 = 0.f, acc1 = 0.f;

    int beg = g_rowptr[n];
    int cnt = g_cnt[n];
    int npair = cnt >> 1;

    // -------- main loop: 2 edges per iteration --------
    int i = beg;
    for (int p = 0; p < npair; p++, i += 2) {
        int sA = g_esrc[i];
        int sB = g_esrc[i + 1];
        // lanes 0-15: edge i attrs; lanes 16-31: edge i+1 attrs (one 128B load)
        float eav = g_eas[(size_t)i * 16 + lane];
        // issue gathers early; consumed after the shfl loop
        float2 xa = *(const float2*)(g_xl + (size_t)sA * 64 + c0);
        float2 xb = *(const float2*)(g_xl + (size_t)sB * 64 + c0);
        float eA0 = 0.f, eA1 = 0.f, eB0 = 0.f, eB1 = 0.f;
#pragma unroll
        for (int k = 0; k < 16; k++) {
            float a  = __shfl_sync(0xffffffffu, eav, k);
            float b  = __shfl_sync(0xffffffffu, eav, 16 + k);
            float2 w = *(const float2*)&Ws[k * 64 + c0];
            eA0 = fmaf(a, w.x, eA0);
            eA1 = fmaf(a, w.y, eA1);
            eB0 = fmaf(b, w.x, eB0);
            eB1 = fmaf(b, w.y, eB1);
        }
        float zA0 = xa.x + xr.x + eA0; zA0 = zA0 > 0.f ? zA0 : 0.2f * zA0;
        float zA1 = xa.y + xr.y + eA1; zA1 = zA1 > 0.f ? zA1 : 0.2f * zA1;
        float zB0 = xb.x + xr.x + eB0; zB0 = zB0 > 0.f ? zB0 : 0.2f * zB0;
        float zB1 = xb.y + xr.y + eB1; zB1 = zB1 > 0.f ? zB1 : 0.2f * zB1;
        float pA = fmaf(zA0, a2.x, zA1 * a2.y);
        float pB = fmaf(zB0, a2.x, zB1 * a2.y);
        if (HEADS8) {
            pA += __shfl_xor_sync(0xffffffffu, pA, 1);
            pA += __shfl_xor_sync(0xffffffffu, pA, 2);
            pB += __shfl_xor_sync(0xffffffffu, pB, 1);
            pB += __shfl_xor_sync(0xffffffffu, pB, 2);
        } else {
#pragma unroll
            for (int o = 1; o < 32; o <<= 1) {
                pA += __shfl_xor_sync(0xffffffffu, pA, o);
                pB += __shfl_xor_sync(0xffffffffu, pB, o);
            }
        }
        float ehA = __expf(pA);       // shift-invariant: no max needed
        float ehB = __expf(pB);
        den += ehA + ehB;
        acc0 = fmaf(ehA, xa.x, acc0);
        acc1 = fmaf(ehA, xa.y, acc1);
        acc0 = fmaf(ehB, xb.x, acc0);
        acc1 = fmaf(ehB, xb.y, acc1);
    }

    // -------- tail: remaining real edge (if cnt odd) + self loop --------
    for (int t = (cnt & 1) ? 0 : 1; t < 2; t++) {
        int src;
        float eav;
        if (t == 0) {                          // last real edge
            src = g_esrc[i];
            eav = (lane < 16) ? g_eas[(size_t)i * 16 + lane] : 0.f;
        } else {                               // self loop
            src = n;
            eav = (lane < 16) ? g_ea_mean[(size_t)n * 16 + lane] : 0.f;
        }
        float2 xa = *(const float2*)(g_xl + (size_t)src * 64 + c0);
        float e0 = 0.f, e1 = 0.f;
#pragma unroll
        for (int k = 0; k < 16; k++) {
            float a  = __shfl_sync(0xffffffffu, eav, k);
            float2 w = *(const float2*)&Ws[k * 64 + c0];
            e0 = fmaf(a, w.x, e0);
            e1 = fmaf(a, w.y, e1);
        }
        float z0 = xa.x + xr.x + e0; z0 = z0 > 0.f ? z0 : 0.2f * z0;
        float z1 = xa.y + xr.y + e1; z1 = z1 > 0.f ? z1 : 0.2f * z1;
        float p = fmaf(z0, a2.x, z1 * a2.y);
        if (HEADS8) {
            p += __shfl_xor_sync(0xffffffffu, p, 1);
            p += __shfl_xor_sync(0xffffffffu, p, 2);
        } else {
#pragma unroll
            for (int o = 1; o < 32; o <<= 1) p += __shfl_xor_sync(0xffffffffu, p, o);
        }
        float eh = __expf(p);
        den += eh;
        acc0 = fmaf(eh, xa.x, acc0);
        acc1 = fmaf(eh, xa.y, acc1);
    }

    float inv = 1.0f / (den + 1e-16f);
    float v0 = acc0 * inv + bs[c0];
    float v1 = acc1 * inv + bs[c0 + 1];
    if (OUTMODE == 0) {
        v0 = v0 > 0.f ? v0 : expm1f(v0);
        v1 = v1 > 0.f ? v1 : expm1f(v1);
        g_h[(size_t)n * 64 + c0]     = v0;
        g_h[(size_t)n * 64 + c0 + 1] = v1;
    } else {
        out[(size_t)n * 64 + c0]     = v0;
        out[(size_t)n * 64 + c0 + 1] = v1;
    }
}

// ---------------- launch (kernel launches ONLY) ----------------------------
extern "C" void kernel_launch(void* const* d_in, const int* in_sizes, int n_in,
                              void* d_out, int out_size) {
    (void)in_sizes; (void)n_in; (void)out_size;
    const float* x    = (const float*)d_in[0];
    const int*   ei   = (const int*)d_in[1];     // int32 (JAX x64 disabled)
    const float* ea   = (const float*)d_in[2];
    const float* Wl1  = (const float*)d_in[3];
    const float* bl1  = (const float*)d_in[4];
    const float* Wr1  = (const float*)d_in[5];
    const float* br1  = (const float*)d_in[6];
    const float* We1  = (const float*)d_in[7];
    const float* att1 = (const float*)d_in[8];
    const float* b1   = (const float*)d_in[9];
    const float* Wl2  = (const float*)d_in[10];
    const float* bl2  = (const float*)d_in[11];
    const float* Wr2  = (const float*)d_in[12];
    const float* br2  = (const float*)d_in[13];
    const float* We2  = (const float*)d_in[14];
    const float* att2 = (const float*)d_in[15];
    const float* b2   = (const float*)d_in[16];
    float* out = (float*)d_out;

    const int TB = 256;
    const int node_blocks = (NN * 32 + TB - 1) / TB;   // warp per node

    // CSR build (+ edge-attr reorder)
    k_zero_cnt<<<(NN + TB - 1) / TB, TB>>>();
    k_hist<<<(NE + TB - 1) / TB, TB>>>(ei);
    k_scan<<<1, 1024>>>();
    k_scatter<<<(NE + TB - 1) / TB, TB>>>(ei, ea);
    k_eamean<<<node_blocks, TB>>>();

    // layer 1
    k_gemm64<128, 0, 0><<<(NN + 63) / 64, 256>>>(x, Wl1, bl1, NN);
    k_gemm64<128, 0, 1><<<(NN + 63) / 64, 256>>>(x, Wr1, br1, NN);
    k_node<1, 0><<<node_blocks, TB>>>(We1, att1, b1, out);

    // layer 2
    k_gemm64<64, 1, 0><<<(NN + 63) / 64, 256>>>(nullptr, Wl2, bl2, NN);
    k_gemm64<64, 1, 1><<<(NN + 63) / 64, 256>>>(nullptr, Wr2, br2, NN);
    k_node<0, 1><<<node_blocks, TB>>>(We2, att2, b2, out);
}